// round 1
// baseline (speedup 1.0000x reference)
#include <cuda_runtime.h>

// Problem constants (fixed by setup_inputs)
#define HW_   262144          // 512*512
#define C_    9
#define N_    16
#define NCH_  144             // N_*C_

// Scratch (device globals — no allocation allowed)
__device__ unsigned g_hist[NCH_ * 2048];
__device__ unsigned g_cand[(size_t)NCH_ * HW_];   // worst-case candidate capture
__device__ float    g_thr[NCH_];

// Order-preserving float<->uint key (ascending key == ascending float)
static __device__ __forceinline__ unsigned f2key(float f) {
    unsigned u = __float_as_uint(f);
    return (u & 0x80000000u) ? ~u : (u | 0x80000000u);
}
static __device__ __forceinline__ float key2f(unsigned k) {
    unsigned u = (k & 0x80000000u) ? (k & 0x7FFFFFFFu) : ~k;
    return __uint_as_float(u);
}

// Warp-aggregated histogram add (callers guarantee full-warp convergence)
static __device__ __forceinline__ void hist_add(unsigned* sh, unsigned bin) {
    unsigned m = __match_any_sync(0xffffffffu, bin);
    unsigned leader = __ffs(m) - 1u;
    if ((threadIdx.x & 31u) == leader) atomicAdd(&sh[bin], (unsigned)__popc(m));
}

// K1: per-channel 2048-bin histogram of key bits [31:21]
__global__ void __launch_bounds__(512) k_hist(const float* __restrict__ inp) {
    __shared__ unsigned sh[2048];
    int ch = blockIdx.x;
    for (int i = threadIdx.x; i < 2048; i += 512) sh[i] = 0;
    __syncthreads();
    const float4* p = (const float4*)(inp + (size_t)ch * HW_);
    // HW_/4 = 65536; 65536/512 = 128 uniform iterations -> full-warp convergence
    for (int i = threadIdx.x; i < HW_ / 4; i += 512) {
        float4 v = p[i];
        hist_add(sh, f2key(v.x) >> 21);
        hist_add(sh, f2key(v.y) >> 21);
        hist_add(sh, f2key(v.z) >> 21);
        hist_add(sh, f2key(v.w) >> 21);
    }
    __syncthreads();
    for (int i = threadIdx.x; i < 2048; i += 512)
        g_hist[ch * 2048 + i] = sh[i];
}

// K2: find candidate bin & rank, capture candidates, refine to exact threshold
__global__ void __launch_bounds__(256) k_select(const float* __restrict__ inp,
                                                const float* __restrict__ ratio) {
    __shared__ unsigned sh[2048];
    __shared__ unsigned s_cnt;
    __shared__ int s_b1, s_r1, s_b2, s_r2;
    int ch = blockIdx.x;
    int n  = ch / C_;

    // Replicate reference f32 arithmetic exactly
    float f_p = floorf(ratio[n] * 262144.0f);
    int   k   = (int)floorf(f_p * 0.15f);
    if (k <= 0) {
        if (threadIdx.x == 0) g_thr[ch] = 1.0f;   // reference: thr = 1 when k == 0
        return;
    }

    for (int i = threadIdx.x; i < 2048; i += 256) sh[i] = g_hist[ch * 2048 + i];
    __syncthreads();
    if (threadIdx.x == 0) {
        int cum = 0;
        for (int b = 2047; b >= 0; b--) {       // walk from largest values down
            int h = (int)sh[b];
            if (cum + h >= k) { s_b1 = b; s_r1 = k - cum; break; }
            cum += h;
        }
        s_cnt = 0;
    }
    __syncthreads();
    unsigned b1 = (unsigned)s_b1;
    int r1 = s_r1;

    // Capture all elements whose top-11 bits match b1 (ballot-aggregated append)
    const float4* p = (const float4*)(inp + (size_t)ch * HW_);
    unsigned* cand  = g_cand + (size_t)ch * HW_;
    unsigned lane = threadIdx.x & 31u;
    unsigned lt   = (1u << lane) - 1u;
    for (int i = threadIdx.x; i < HW_ / 4; i += 256) {   // 256 uniform iterations
        float4 v = p[i];
        unsigned kk[4] = { f2key(v.x), f2key(v.y), f2key(v.z), f2key(v.w) };
        #pragma unroll
        for (int j = 0; j < 4; j++) {
            bool sel = (kk[j] >> 21) == b1;
            unsigned bm = __ballot_sync(0xffffffffu, sel);
            if (bm) {
                unsigned base = 0;
                if (lane == 0) base = atomicAdd(&s_cnt, (unsigned)__popc(bm));
                base = __shfl_sync(0xffffffffu, base, 0);
                if (sel) cand[base + __popc(bm & lt)] = kk[j];
            }
        }
    }
    __syncthreads();
    int m = (int)s_cnt;

    // Level 2: bits [20:10] among candidates
    for (int i = threadIdx.x; i < 2048; i += 256) sh[i] = 0;
    __syncthreads();
    for (int i = threadIdx.x; i < m; i += 256)
        atomicAdd(&sh[(cand[i] >> 10) & 0x7FFu], 1u);
    __syncthreads();
    if (threadIdx.x == 0) {
        int cum = 0;
        for (int b = 2047; b >= 0; b--) {
            int h = (int)sh[b];
            if (cum + h >= r1) { s_b2 = b; s_r2 = r1 - cum; break; }
            cum += h;
        }
    }
    __syncthreads();
    unsigned b2 = (unsigned)s_b2;
    int r2 = s_r2;

    // Level 3: bits [9:0] among doubly-filtered candidates -> exact 32-bit key
    for (int i = threadIdx.x; i < 1024; i += 256) sh[i] = 0;
    __syncthreads();
    for (int i = threadIdx.x; i < m; i += 256) {
        unsigned kv = cand[i];
        if (((kv >> 10) & 0x7FFu) == b2) atomicAdd(&sh[kv & 0x3FFu], 1u);
    }
    __syncthreads();
    if (threadIdx.x == 0) {
        int cum = 0;
        for (int b = 1023; b >= 0; b--) {
            int h = (int)sh[b];
            if (cum + h >= r2) {
                unsigned key = (b1 << 21) | (b2 << 10) | (unsigned)b;
                g_thr[ch] = key2f(key);
                break;
            }
            cum += h;
        }
    }
}

// K3: mask & write output. OR over 9 channels of (inp > thr), zero those pixels.
__global__ void __launch_bounds__(256) k_mask(const float* __restrict__ inp,
                                              const float* __restrict__ x,
                                              float* __restrict__ out) {
    __shared__ float sthr[C_];
    int n = blockIdx.y;
    if (threadIdx.x < C_) sthr[threadIdx.x] = g_thr[n * C_ + threadIdx.x];
    __syncthreads();
    int i = blockIdx.x * 256 + threadIdx.x;          // 0 .. HW_/4 - 1
    float4 xv = ((const float4*)(x + (size_t)n * HW_))[i];
    bool mx = false, my = false, mz = false, mw = false;
    const float* base = inp + (size_t)n * C_ * HW_;
    #pragma unroll
    for (int c = 0; c < C_; c++) {
        float t = sthr[c];
        float4 v = ((const float4*)(base + (size_t)c * HW_))[i];
        mx |= v.x > t; my |= v.y > t; mz |= v.z > t; mw |= v.w > t;
    }
    float4 o;
    o.x = mx ? 0.0f : xv.x;
    o.y = my ? 0.0f : xv.y;
    o.z = mz ? 0.0f : xv.z;
    o.w = mw ? 0.0f : xv.w;
    ((float4*)out)[(size_t)n * (HW_ / 4) + i] = o;
}

extern "C" void kernel_launch(void* const* d_in, const int* in_sizes, int n_in,
                              void* d_out, int out_size) {
    const float* inp   = (const float*)d_in[0];   // [16,9,512,512]
    const float* x     = (const float*)d_in[1];   // [16,1,512,512]
    const float* ratio = (const float*)d_in[2];   // [16]
    float* out = (float*)d_out;

    k_hist<<<NCH_, 512>>>(inp);
    k_select<<<NCH_, 256>>>(inp, ratio);
    dim3 g(HW_ / 4 / 256, N_);
    k_mask<<<g, 256>>>(inp, x, out);
}

// round 2
// speedup vs baseline: 2.0511x; 2.0511x over previous
#include <cuda_runtime.h>

#define HW_   262144          // 512*512
#define C_    9
#define N_    16
#define NCH_  144             // N_*C_
#define NT_   512             // threads per CTA in k_main
#define NW_   16              // warps per CTA
#define NB1_  2048            // level-1 bins (key bits [31:21])

// Scratch (device globals — no allocation allowed)
__device__ unsigned long long g_cand[(size_t)NCH_ * HW_];  // (key<<32)|pos, worst case
__device__ unsigned g_bitmap[NCH_ * (HW_ / 32)];           // per-channel mask bitmap

// Order-preserving float->uint key (ascending key == ascending float)
static __device__ __forceinline__ unsigned f2key(float f) {
    unsigned u = __float_as_uint(f);
    return (u & 0x80000000u) ? ~u : (u | 0x80000000u);
}

// Block-wide "find bin containing rank-from-top" over hist[0..nb), nb in {2048,1024}.
// Returns bin and remaining rank (1-indexed within that bin) via aux[0], aux[1].
// All 512 threads must call. hist must be finalized (caller synced).
static __device__ __forceinline__ void block_find_bin(
    unsigned* hist, int nb, unsigned rank,
    unsigned* sgrp, unsigned* aux, int tid, int lane, int w)
{
    int B = nb >> 9;                        // bins per group (4 or 2)
    unsigned s = 0;
    #pragma unroll
    for (int j = 0; j < 4; j++) if (j < B) s += hist[tid * B + j];
    sgrp[tid] = s;
    __syncthreads();
    if (w == 0) {
        unsigned sup = 0;
        #pragma unroll
        for (int j = 0; j < 16; j++) sup += sgrp[lane * 16 + j];
        // inclusive suffix scan over lanes (lane31 = highest bins)
        unsigned v = sup;
        #pragma unroll
        for (int off = 1; off < 32; off <<= 1) {
            unsigned t = __shfl_down_sync(0xffffffffu, v, off);
            if (lane + off < 32) v += t;
        }
        unsigned cumAbove = v - sup;        // sum of sup[j], j > lane
        bool hit = (cumAbove < rank) && (cumAbove + sup >= rank);
        unsigned bal = __ballot_sync(0xffffffffu, hit);
        int Ls = __ffs(bal) - 1;
        if (lane == Ls) {
            unsigned cum = cumAbove;
            for (int g = Ls * 16 + 15; g >= Ls * 16; g--) {
                unsigned sg = sgrp[g];
                if (cum + sg >= rank) {
                    for (int b = g * B + B - 1; ; b--) {
                        unsigned h = hist[b];
                        if (cum + h >= rank) { aux[0] = (unsigned)b; aux[1] = rank - cum; break; }
                        cum += h;
                    }
                    break;
                }
                cum += sg;
            }
        }
    }
    __syncthreads();
}

// K_main: per-channel (144 CTAs). Histogram -> b1/r1 -> rescan (definite mask bits +
// candidate capture) -> 2-level refinement to exact threshold -> bitmap fixups -> write bitmap.
__global__ void __launch_bounds__(NT_) k_main(const float* __restrict__ inp,
                                              const float* __restrict__ ratio)
{
    extern __shared__ unsigned smem_[];
    unsigned* hist = smem_;                       // NW_*NB1_  (warp-private level-1 hists)
    unsigned* sbm  = hist + NW_ * NB1_;           // 8192 (channel mask bitmap)
    unsigned* sgrp = sbm + 8192;                  // 512
    unsigned* aux  = sgrp + 512;                  // [0]=bin [1]=rank [2]=cand count

    int ch = blockIdx.x, n = ch / C_;
    int tid = threadIdx.x, w = tid >> 5, lane = tid & 31;
    unsigned lt = (1u << lane) - 1u;

    for (int i = tid; i < NW_ * NB1_; i += NT_) hist[i] = 0;
    for (int i = tid; i < 8192; i += NT_) sbm[i] = 0;
    if (tid == 0) aux[2] = 0;
    __syncthreads();

    const float4* p = (const float4*)(inp + (size_t)ch * HW_);
    unsigned* myh = hist + w * NB1_;

    // ---- pass 1: per-warp privatized level-1 histogram (key bits [31:21]) ----
    for (int base = 0; base < HW_ / 4; base += 4 * NT_) {
        float4 v0 = p[base + tid];
        float4 v1 = p[base + tid + NT_];
        float4 v2 = p[base + tid + 2 * NT_];
        float4 v3 = p[base + tid + 3 * NT_];
        atomicAdd(&myh[f2key(v0.x) >> 21], 1u); atomicAdd(&myh[f2key(v0.y) >> 21], 1u);
        atomicAdd(&myh[f2key(v0.z) >> 21], 1u); atomicAdd(&myh[f2key(v0.w) >> 21], 1u);
        atomicAdd(&myh[f2key(v1.x) >> 21], 1u); atomicAdd(&myh[f2key(v1.y) >> 21], 1u);
        atomicAdd(&myh[f2key(v1.z) >> 21], 1u); atomicAdd(&myh[f2key(v1.w) >> 21], 1u);
        atomicAdd(&myh[f2key(v2.x) >> 21], 1u); atomicAdd(&myh[f2key(v2.y) >> 21], 1u);
        atomicAdd(&myh[f2key(v2.z) >> 21], 1u); atomicAdd(&myh[f2key(v2.w) >> 21], 1u);
        atomicAdd(&myh[f2key(v3.x) >> 21], 1u); atomicAdd(&myh[f2key(v3.y) >> 21], 1u);
        atomicAdd(&myh[f2key(v3.z) >> 21], 1u); atomicAdd(&myh[f2key(v3.w) >> 21], 1u);
    }
    __syncthreads();

    // reduce 16 warp hists into hist[0..2047] (bin b touched only by thread b%512)
    for (int b = tid; b < NB1_; b += NT_) {
        unsigned s = 0;
        #pragma unroll
        for (int ww = 0; ww < NW_; ww++) s += hist[ww * NB1_ + b];
        hist[b] = s;
    }
    __syncthreads();

    // ---- k and level-1 selection (replicate reference f32 arithmetic) ----
    float f_p = floorf(ratio[n] * 262144.0f);
    int k = (int)floorf(f_p * 0.15f);
    bool k0 = (k <= 0);                 // reference: thr = 1.0 when k == 0
    int b1 = 0; unsigned r1 = 0;
    if (!k0) {
        block_find_bin(hist, NB1_, (unsigned)k, sgrp, aux, tid, lane, w);
        b1 = (int)aux[0]; r1 = aux[1];
    }
    const unsigned K1REF = 0xBF800000u; // f2key(1.0f)
    unsigned ub1 = (unsigned)b1;
    unsigned long long* cd = g_cand + (size_t)ch * HW_;

    // ---- pass 2: definite mask bits + candidate capture ----
    for (int base = 0; base < HW_ / 4; base += 4 * NT_) {
        #pragma unroll
        for (int j = 0; j < 4; j++) {
            int idx = base + tid + j * NT_;
            float4 v = p[idx];
            unsigned kk[4] = { f2key(v.x), f2key(v.y), f2key(v.z), f2key(v.w) };
            unsigned nib;
            if (k0) {
                nib = (unsigned)(kk[0] > K1REF) | ((unsigned)(kk[1] > K1REF) << 1)
                    | ((unsigned)(kk[2] > K1REF) << 2) | ((unsigned)(kk[3] > K1REF) << 3);
            } else {
                nib = (unsigned)((kk[0] >> 21) > ub1) | ((unsigned)((kk[1] >> 21) > ub1) << 1)
                    | ((unsigned)((kk[2] >> 21) > ub1) << 2) | ((unsigned)((kk[3] >> 21) > ub1) << 3);
            }
            if (nib) atomicOr(&sbm[idx >> 3], nib << ((idx & 7) * 4));
            if (!k0) {
                #pragma unroll
                for (int e = 0; e < 4; e++) {
                    bool sel = (kk[e] >> 21) == ub1;
                    unsigned bm = __ballot_sync(0xffffffffu, sel);
                    if (bm) {
                        unsigned pos0 = 0;
                        if (lane == 0) pos0 = atomicAdd(&aux[2], (unsigned)__popc(bm));
                        pos0 = __shfl_sync(0xffffffffu, pos0, 0);
                        if (sel)
                            cd[pos0 + __popc(bm & lt)] =
                                ((unsigned long long)kk[e] << 32) | (unsigned)(idx * 4 + e);
                    }
                }
            }
        }
    }
    __syncthreads();

    if (!k0) {
        int m = (int)aux[2];
        // ---- level 2: key bits [20:10] among candidates ----
        for (int i = tid; i < NB1_; i += NT_) hist[i] = 0;
        __syncthreads();
        for (int i = tid; i < m; i += NT_)
            atomicAdd(&hist[((unsigned)(cd[i] >> 32) >> 10) & 0x7FFu], 1u);
        __syncthreads();
        block_find_bin(hist, 2048, r1, sgrp, aux, tid, lane, w);
        unsigned b2 = aux[0], r2 = aux[1];
        __syncthreads();
        // ---- level 3: key bits [9:0] ----
        for (int i = tid; i < 1024; i += NT_) hist[i] = 0;
        __syncthreads();
        for (int i = tid; i < m; i += NT_) {
            unsigned key = (unsigned)(cd[i] >> 32);
            if (((key >> 10) & 0x7FFu) == b2) atomicAdd(&hist[key & 0x3FFu], 1u);
        }
        __syncthreads();
        block_find_bin(hist, 1024, r2, sgrp, aux, tid, lane, w);
        unsigned b3 = aux[0];
        unsigned thrkey = (ub1 << 21) | (b2 << 10) | b3;   // exact key of k-th largest
        __syncthreads();
        // ---- fixups: candidates strictly above threshold ----
        for (int i = tid; i < m; i += NT_) {
            unsigned long long c = cd[i];
            unsigned key = (unsigned)(c >> 32);
            if (key > thrkey) {
                unsigned pos = (unsigned)c & 0x3FFFFu;
                atomicOr(&sbm[pos >> 5], 1u << (pos & 31u));
            }
        }
        __syncthreads();
    }

    // ---- write per-channel bitmap (full overwrite, no pre-zero needed) ----
    for (int j = tid; j < 8192; j += NT_)
        g_bitmap[(size_t)ch * 8192 + j] = sbm[j];
}

// K_mask: OR the 9 channel bitmaps, apply to x.
__global__ void __launch_bounds__(256) k_mask(const float* __restrict__ x,
                                              float* __restrict__ out)
{
    int n = blockIdx.y;
    int i = blockIdx.x * 256 + threadIdx.x;          // float4 index within sample
    const unsigned* bm = g_bitmap + (size_t)n * C_ * 8192 + (i >> 3);
    unsigned wrd = 0;
    #pragma unroll
    for (int c = 0; c < C_; c++) wrd |= bm[(size_t)c * 8192];
    unsigned nib = (wrd >> ((i & 7) * 4)) & 0xFu;
    float4 xv = ((const float4*)(x + (size_t)n * HW_))[i];
    float4 o;
    o.x = (nib & 1u) ? 0.0f : xv.x;
    o.y = (nib & 2u) ? 0.0f : xv.y;
    o.z = (nib & 4u) ? 0.0f : xv.z;
    o.w = (nib & 8u) ? 0.0f : xv.w;
    ((float4*)out)[(size_t)n * (HW_ / 4) + i] = o;
}

extern "C" void kernel_launch(void* const* d_in, const int* in_sizes, int n_in,
                              void* d_out, int out_size) {
    const float* inp   = (const float*)d_in[0];   // [16,9,512,512]
    const float* x     = (const float*)d_in[1];   // [16,1,512,512]
    const float* ratio = (const float*)d_in[2];   // [16]
    float* out = (float*)d_out;

    const int smem_bytes = (NW_ * NB1_ + 8192 + 512 + 16) * 4;   // ~166 KB
    cudaFuncSetAttribute(k_main, cudaFuncAttributeMaxDynamicSharedMemorySize, smem_bytes);

    k_main<<<NCH_, NT_, smem_bytes>>>(inp, ratio);
    dim3 g(HW_ / 4 / 256, N_);
    k_mask<<<g, 256>>>(x, out);
}

// round 3
// speedup vs baseline: 2.6351x; 1.2847x over previous
#include <cuda_runtime.h>

#define HW_   262144          // 512*512
#define C_    9
#define N_    16
#define NCH_  144             // N_*C_
#define NT_   512             // threads per CTA in k_main

// Scratch (device globals — no allocation allowed)
__device__ unsigned long long g_cand[(size_t)NCH_ * HW_];  // (key<<32)|pos
__device__ unsigned g_bitmap[NCH_ * (HW_ / 32)];           // per-channel mask bitmap

// Order-preserving float<->uint key (ascending key == ascending float)
static __device__ __forceinline__ unsigned f2key(float f) {
    unsigned u = __float_as_uint(f);
    return (u & 0x80000000u) ? ~u : (u | 0x80000000u);
}
static __device__ __forceinline__ float key2f(unsigned k) {
    unsigned u = (k & 0x80000000u) ? (k & 0x7FFFFFFFu) : ~k;
    return __uint_as_float(u);
}

// Block-wide "find bin containing rank-from-top" over hist[0..nb), nb in {2048,1024}.
// Result in aux[0]=bin, aux[1]=remaining rank. All NT_ threads call; hist finalized.
static __device__ __forceinline__ void block_find_bin(
    unsigned* hist, int nb, unsigned rank,
    unsigned* sgrp, unsigned* aux, int tid, int lane, int w)
{
    int B = nb >> 9;                        // bins per thread-group (4 or 2)
    unsigned s = 0;
    #pragma unroll
    for (int j = 0; j < 4; j++) if (j < B) s += hist[tid * B + j];
    sgrp[tid] = s;
    __syncthreads();
    if (w == 0) {
        unsigned sup = 0;
        #pragma unroll
        for (int j = 0; j < 16; j++) sup += sgrp[lane * 16 + j];
        unsigned v = sup;                   // inclusive suffix scan (lane31 = top bins)
        #pragma unroll
        for (int off = 1; off < 32; off <<= 1) {
            unsigned t = __shfl_down_sync(0xffffffffu, v, off);
            if (lane + off < 32) v += t;
        }
        unsigned cumAbove = v - sup;
        bool hit = (cumAbove < rank) && (cumAbove + sup >= rank);
        unsigned bal = __ballot_sync(0xffffffffu, hit);
        int Ls = __ffs(bal) - 1;
        if (lane == Ls) {
            unsigned cum = cumAbove;
            for (int g = Ls * 16 + 15; g >= Ls * 16; g--) {
                unsigned sg = sgrp[g];
                if (cum + sg >= rank) {
                    for (int b = g * B + B - 1; ; b--) {
                        unsigned h = hist[b];
                        if (cum + h >= rank) { aux[0] = (unsigned)b; aux[1] = rank - cum; break; }
                        cum += h;
                    }
                    break;
                }
                cum += sg;
            }
        }
    }
    __syncthreads();
}

__global__ void __launch_bounds__(NT_) k_main(const float* __restrict__ inp,
                                              const float* __restrict__ ratio)
{
    __shared__ unsigned hist[2048];
    __shared__ unsigned sbm[8192];     // channel mask bitmap (1 bit / pixel)
    __shared__ unsigned sgrp[512];
    __shared__ unsigned aux[8];        // [0]bin [1]rank [2]cand-count [3]above-count

    int ch = blockIdx.x, n = ch / C_;
    int tid = threadIdx.x, w = tid >> 5, lane = tid & 31;
    unsigned lt = (1u << lane) - 1u;

    // k: replicate reference f32 arithmetic exactly
    float f_p = floorf(ratio[n] * 262144.0f);
    int k = (int)floorf(f_p * 0.15f);
    bool k0 = (k <= 0);

    const float4* p = (const float4*)(inp + (size_t)ch * HW_);
    const float INF = __int_as_float(0x7F800000);

    float lo_f, hi_f;
    if (k0) {
        lo_f = hi_f = 1.0f;            // reference: thr = 1.0 when k == 0 (strict >)
    } else {
        // ---- sample phase: 2048 strided float4 = 8192 elements ----
        for (int i = tid; i < 2048; i += NT_) hist[i] = 0;
        __syncthreads();
        #pragma unroll
        for (int j = 0; j < 4; j++) {
            float4 v = p[(tid + j * NT_) * 32];
            atomicAdd(&hist[f2key(v.x) >> 21], 1u);
            atomicAdd(&hist[f2key(v.y) >> 21], 1u);
            atomicAdd(&hist[f2key(v.z) >> 21], 1u);
            atomicAdd(&hist[f2key(v.w) >> 21], 1u);
        }
        __syncthreads();
        int ks = k >> 5;                              // sample-space rank ~ k/32
        unsigned rank_hi = (unsigned)max(1, ks - 384);
        unsigned rank_lo = (unsigned)min(8192, ks + 384);
        block_find_bin(hist, 2048, rank_hi, sgrp, aux, tid, lane, w);
        unsigned b_hi = aux[0];
        block_find_bin(hist, 2048, rank_lo, sgrp, aux, tid, lane, w);
        unsigned b_lo = aux[0];
        unsigned hk = ((b_hi + 1u) << 21) - 1u;       // upper edge of hi bin
        hi_f = (hk >= 0xFF800000u) ? INF : key2f(hk);
        if (b_lo == 0) lo_f = -INF;
        else {
            unsigned lk = (b_lo << 21) - 1u;          // just below lo bin
            lo_f = (lk <= 0x007FFFFFu) ? -INF : key2f(lk);
        }
    }

    // ---- streaming pass: definite mask bits + candidate capture ----
    unsigned long long* cd = g_cand + (size_t)ch * HW_;
    unsigned cnt_hi = 0, m = 0;
    for (int attempt = 0; ; attempt++) {
        __syncthreads();
        if (tid == 0) { aux[2] = 0; aux[3] = 0; }
        __syncthreads();
        unsigned mycnt = 0;
        for (int base = 0; base < HW_ / 4; base += 4 * NT_) {
            #pragma unroll
            for (int j = 0; j < 4; j++) {
                int idx = base + j * NT_ + tid;
                float4 v = p[idx];
                unsigned ab = (unsigned)(v.x > hi_f) | ((unsigned)(v.y > hi_f) << 1)
                            | ((unsigned)(v.z > hi_f) << 2) | ((unsigned)(v.w > hi_f) << 3);
                unsigned gl = (unsigned)(v.x > lo_f) | ((unsigned)(v.y > lo_f) << 1)
                            | ((unsigned)(v.z > lo_f) << 2) | ((unsigned)(v.w > lo_f) << 3);
                unsigned cn = gl & ~ab;
                mycnt += __popc(ab);
                unsigned word = ab << ((lane & 7) * 4);
                word |= __shfl_xor_sync(0xffffffffu, word, 1);
                word |= __shfl_xor_sync(0xffffffffu, word, 2);
                word |= __shfl_xor_sync(0xffffffffu, word, 4);
                if ((lane & 7) == 0) sbm[idx >> 3] = word;
                #pragma unroll
                for (int e = 0; e < 4; e++) {
                    bool sel = (cn >> e) & 1u;
                    unsigned bm = __ballot_sync(0xffffffffu, sel);
                    if (bm) {
                        unsigned pos0 = 0;
                        if (lane == 0) pos0 = atomicAdd(&aux[2], (unsigned)__popc(bm));
                        pos0 = __shfl_sync(0xffffffffu, pos0, 0);
                        if (sel) {
                            float fv = (e == 0) ? v.x : (e == 1) ? v.y : (e == 2) ? v.z : v.w;
                            cd[pos0 + __popc(bm & lt)] =
                                ((unsigned long long)f2key(fv) << 32) | (unsigned)(idx * 4 + e);
                        }
                    }
                }
            }
        }
        #pragma unroll
        for (int off = 16; off; off >>= 1) mycnt += __shfl_down_sync(0xffffffffu, mycnt, off);
        if (lane == 0) atomicAdd(&aux[3], mycnt);
        __syncthreads();
        cnt_hi = aux[3]; m = aux[2];
        if (k0) break;
        if ((cnt_hi < (unsigned)k && cnt_hi + m >= (unsigned)k) || attempt >= 1) break;
        lo_f = -INF; hi_f = INF;       // deterministic widen (astronomically rare)
    }

    // ---- exact threshold among candidates, then bitmap fixups ----
    if (!k0) {
        unsigned r = (unsigned)k - cnt_hi;
        for (int i = tid; i < 2048; i += NT_) hist[i] = 0;
        __syncthreads();
        for (unsigned i = tid; i < m; i += NT_)
            atomicAdd(&hist[(unsigned)(cd[i] >> 32) >> 21], 1u);
        __syncthreads();
        block_find_bin(hist, 2048, r, sgrp, aux, tid, lane, w);
        unsigned bA = aux[0], rA = aux[1];
        __syncthreads();
        for (int i = tid; i < 2048; i += NT_) hist[i] = 0;
        __syncthreads();
        for (unsigned i = tid; i < m; i += NT_) {
            unsigned key = (unsigned)(cd[i] >> 32);
            if ((key >> 21) == bA) atomicAdd(&hist[(key >> 10) & 0x7FFu], 1u);
        }
        __syncthreads();
        block_find_bin(hist, 2048, rA, sgrp, aux, tid, lane, w);
        unsigned bB = aux[0], rB = aux[1];
        __syncthreads();
        for (int i = tid; i < 1024; i += NT_) hist[i] = 0;
        __syncthreads();
        for (unsigned i = tid; i < m; i += NT_) {
            unsigned key = (unsigned)(cd[i] >> 32);
            if ((key >> 21) == bA && ((key >> 10) & 0x7FFu) == bB)
                atomicAdd(&hist[key & 0x3FFu], 1u);
        }
        __syncthreads();
        block_find_bin(hist, 1024, rB, sgrp, aux, tid, lane, w);
        unsigned thrkey = (bA << 21) | (bB << 10) | aux[0];
        __syncthreads();
        for (unsigned i = tid; i < m; i += NT_) {
            unsigned long long c = cd[i];
            if ((unsigned)(c >> 32) > thrkey) {
                unsigned pos = (unsigned)c & 0x3FFFFu;
                atomicOr(&sbm[pos >> 5], 1u << (pos & 31u));
            }
        }
        __syncthreads();
    }

    for (int j = tid; j < 8192; j += NT_)
        g_bitmap[(size_t)ch * 8192 + j] = sbm[j];
}

// K_mask: OR 9 channel bitmaps (smem-staged), apply to x.
__global__ void __launch_bounds__(256) k_mask(const float* __restrict__ x,
                                              float* __restrict__ out)
{
    __shared__ unsigned sw[32];
    int n = blockIdx.y;
    int i = blockIdx.x * 256 + threadIdx.x;          // float4 index within sample
    if (threadIdx.x < 32) {
        const unsigned* bm = g_bitmap + (size_t)n * C_ * 8192
                           + (size_t)blockIdx.x * 32 + threadIdx.x;
        unsigned o = 0;
        #pragma unroll
        for (int c = 0; c < C_; c++) o |= bm[(size_t)c * 8192];
        sw[threadIdx.x] = o;
    }
    __syncthreads();
    unsigned nib = (sw[threadIdx.x >> 3] >> ((threadIdx.x & 7) * 4)) & 0xFu;
    float4 xv = ((const float4*)(x + (size_t)n * HW_))[i];
    float4 o;
    o.x = (nib & 1u) ? 0.0f : xv.x;
    o.y = (nib & 2u) ? 0.0f : xv.y;
    o.z = (nib & 4u) ? 0.0f : xv.z;
    o.w = (nib & 8u) ? 0.0f : xv.w;
    ((float4*)out)[(size_t)n * (HW_ / 4) + i] = o;
}

extern "C" void kernel_launch(void* const* d_in, const int* in_sizes, int n_in,
                              void* d_out, int out_size) {
    const float* inp   = (const float*)d_in[0];   // [16,9,512,512]
    const float* x     = (const float*)d_in[1];   // [16,1,512,512]
    const float* ratio = (const float*)d_in[2];   // [16]
    float* out = (float*)d_out;

    k_main<<<NCH_, NT_>>>(inp, ratio);
    dim3 g(HW_ / 4 / 256, N_);
    k_mask<<<g, 256>>>(x, out);
}

// round 4
// speedup vs baseline: 4.8070x; 1.8243x over previous
#include <cuda_runtime.h>

#define HW_   262144          // 512*512
#define C_    9
#define N_    16
#define NCH_  144             // N_*C_
#define NT_   1024            // threads per CTA in k_main
#define NW_   32              // warps per CTA
#define CAP_  (HW_ / NW_)     // 8192 candidate slots per warp region (hard bound)

// Scratch (device globals — no allocation allowed)
__device__ unsigned long long g_cand[(size_t)NCH_ * HW_];  // per-warp regions: (key<<32)|pos
__device__ unsigned g_bitmap[NCH_ * (HW_ / 32)];           // per-channel mask bitmap

// Order-preserving float->uint key (ascending key == ascending float)
static __device__ __forceinline__ unsigned f2key(float f) {
    unsigned u = __float_as_uint(f);
    return (u & 0x80000000u) ? ~u : (u | 0x80000000u);
}

// Block-wide "find bin containing rank-from-top" over hist[0..nb), nb in {2048,1024}.
// Result: aux[0]=bin, aux[1]=remaining rank (1-indexed in bin). All NT_ threads call.
static __device__ __forceinline__ void block_find_bin(
    unsigned* hist, int nb, unsigned rank,
    unsigned* sgrp, unsigned* aux, int tid, int lane, int w)
{
    unsigned s = (nb == 2048) ? (hist[tid * 2] + hist[tid * 2 + 1]) : hist[tid];
    sgrp[tid] = s;
    __syncthreads();
    if (w == 0) {
        unsigned sup = 0;
        #pragma unroll 4
        for (int j = 0; j < 32; j++) sup += sgrp[lane * 32 + j];
        unsigned v = sup;                    // inclusive suffix scan (lane31 = top bins)
        #pragma unroll
        for (int off = 1; off < 32; off <<= 1) {
            unsigned t = __shfl_down_sync(0xffffffffu, v, off);
            if (lane + off < 32) v += t;
        }
        unsigned cumAbove = v - sup;
        bool hit = (cumAbove < rank) && (cumAbove + sup >= rank);
        unsigned bal = __ballot_sync(0xffffffffu, hit);
        int Ls = __ffs(bal) - 1;
        if (lane == Ls) {
            unsigned cum = cumAbove;
            for (int g = Ls * 32 + 31; ; g--) {
                unsigned sg = sgrp[g];
                if (cum + sg >= rank) {
                    int B = (nb == 2048) ? 2 : 1;
                    for (int b = g * B + B - 1; ; b--) {
                        unsigned h = hist[b];
                        if (cum + h >= rank) { aux[0] = (unsigned)b; aux[1] = rank - cum; break; }
                        cum += h;
                    }
                    break;
                }
                cum += sg;
            }
        }
    }
    __syncthreads();
}

__global__ void __launch_bounds__(NT_) k_main(const float* __restrict__ inp,
                                              const float* __restrict__ ratio)
{
    __shared__ unsigned hist[2048];
    __shared__ unsigned sbm[8192];     // channel mask bitmap (1 bit / pixel)
    __shared__ unsigned sgrp[NT_];
    __shared__ unsigned wcnt[NW_];
    __shared__ unsigned aux[4];        // [0]=above-count / bin, [1]=m / rank

    int ch = blockIdx.x, n = ch / C_;
    int tid = threadIdx.x, w = tid >> 5, lane = tid & 31;
    unsigned lt = (1u << lane) - 1u;

    // k: replicate reference f32 arithmetic exactly
    float f_p = floorf(ratio[n] * 262144.0f);
    int k = (int)floorf(f_p * 0.15f);
    bool k0 = (k <= 0);

    const float4* p = (const float4*)(inp + (size_t)ch * HW_);
    const float INF = __int_as_float(0x7F800000);

    // Analytic bracket around the k-th largest of N(0,1) data. Correctness is
    // guaranteed by the count-check + full-range retry below, not by normality.
    float lo_f, hi_f;
    if (k0) {
        lo_f = hi_f = 1.0f;            // reference: thr = 1.0 when k == 0 (strict >)
    } else {
        float q = (float)k * (1.0f / 262144.0f);        // tail prob, (0, 0.15]
        float t = sqrtf(-2.0f * logf(q));               // A&S 26.2.23, |err| < 4.5e-4
        float z = t - (2.515517f + 0.802853f * t + 0.010328f * t * t)
                    / (1.0f + 1.432788f * t + 0.189269f * t * t + 0.001308f * t * t * t);
        float phi = 0.3989423f * expf(-0.5f * z * z);
        float delta = 0.008f + 10.0f * sqrtf((float)k) / (262144.0f * phi);
        lo_f = z - delta; hi_f = z + delta;
    }

    unsigned long long* cd = g_cand + (size_t)ch * HW_;
    unsigned cnt_hi, m;
    for (int attempt = 0; ; attempt++) {
        if (tid == 0) aux[0] = 0;
        __syncthreads();
        unsigned mycnt = 0;
        unsigned wbase = 0;                                    // warp-uniform
        unsigned long long* wcd = cd + (size_t)w * CAP_;
        #pragma unroll 4
        for (int base = 0; base < HW_ / 4; base += NT_) {
            int idx = base + tid;
            float4 v = p[idx];
            unsigned ab = (unsigned)(v.x > hi_f) | ((unsigned)(v.y > hi_f) << 1)
                        | ((unsigned)(v.z > hi_f) << 2) | ((unsigned)(v.w > hi_f) << 3);
            unsigned gl = (unsigned)(v.x > lo_f) | ((unsigned)(v.y > lo_f) << 1)
                        | ((unsigned)(v.z > lo_f) << 2) | ((unsigned)(v.w > lo_f) << 3);
            unsigned cn = gl & ~ab;
            mycnt += __popc(ab);
            unsigned word = ab << ((lane & 7) * 4);            // pack 8 threads -> 32-bit
            word |= __shfl_xor_sync(0xffffffffu, word, 1);
            word |= __shfl_xor_sync(0xffffffffu, word, 2);
            word |= __shfl_xor_sync(0xffffffffu, word, 4);
            if ((lane & 7) == 0) sbm[idx >> 3] = word;
            #pragma unroll
            for (int e = 0; e < 4; e++) {                      // branch-free capture
                bool sel = (cn >> e) & 1u;
                unsigned bm = __ballot_sync(0xffffffffu, sel);
                if (sel) {
                    float fv = (e == 0) ? v.x : (e == 1) ? v.y : (e == 2) ? v.z : v.w;
                    wcd[wbase + __popc(bm & lt)] =
                        ((unsigned long long)f2key(fv) << 32) | (unsigned)(idx * 4 + e);
                }
                wbase += __popc(bm);
            }
        }
        if (lane == 0) wcnt[w] = wbase;
        #pragma unroll
        for (int off = 16; off; off >>= 1) mycnt += __shfl_down_sync(0xffffffffu, mycnt, off);
        if (lane == 0) atomicAdd(&aux[0], mycnt);
        __syncthreads();
        cnt_hi = aux[0];
        if (w == 0) {
            unsigned c = wcnt[lane];
            #pragma unroll
            for (int off = 16; off; off >>= 1) c += __shfl_down_sync(0xffffffffu, c, off);
            if (lane == 0) aux[1] = c;
        }
        __syncthreads();
        m = aux[1];
        if (k0) break;
        if ((cnt_hi < (unsigned)k && cnt_hi + m >= (unsigned)k) || attempt >= 1) break;
        lo_f = -INF; hi_f = INF;       // deterministic widen (never for N(0,1) data)
        __syncthreads();
    }

    // ---- exact threshold among candidates (11 + 11 + 10 bit radix), then fixups ----
    if (!k0) {
        unsigned r = (unsigned)k - cnt_hi;
        for (int i = tid; i < 2048; i += NT_) hist[i] = 0;
        __syncthreads();
        for (int ww = 0; ww < NW_; ww++) {
            unsigned c = wcnt[ww];
            const unsigned long long* rg = cd + (size_t)ww * CAP_;
            for (unsigned i = tid; i < c; i += NT_)
                atomicAdd(&hist[(unsigned)(rg[i] >> 32) >> 21], 1u);
        }
        __syncthreads();
        block_find_bin(hist, 2048, r, sgrp, aux, tid, lane, w);
        unsigned bA = aux[0], rA = aux[1];
        __syncthreads();

        for (int i = tid; i < 2048; i += NT_) hist[i] = 0;
        __syncthreads();
        for (int ww = 0; ww < NW_; ww++) {
            unsigned c = wcnt[ww];
            const unsigned long long* rg = cd + (size_t)ww * CAP_;
            for (unsigned i = tid; i < c; i += NT_) {
                unsigned key = (unsigned)(rg[i] >> 32);
                if ((key >> 21) == bA) atomicAdd(&hist[(key >> 10) & 0x7FFu], 1u);
            }
        }
        __syncthreads();
        block_find_bin(hist, 2048, rA, sgrp, aux, tid, lane, w);
        unsigned bB = aux[0], rB = aux[1];
        __syncthreads();

        for (int i = tid; i < 1024; i += NT_) hist[i] = 0;
        __syncthreads();
        for (int ww = 0; ww < NW_; ww++) {
            unsigned c = wcnt[ww];
            const unsigned long long* rg = cd + (size_t)ww * CAP_;
            for (unsigned i = tid; i < c; i += NT_) {
                unsigned key = (unsigned)(rg[i] >> 32);
                if ((key >> 21) == bA && ((key >> 10) & 0x7FFu) == bB)
                    atomicAdd(&hist[key & 0x3FFu], 1u);
            }
        }
        __syncthreads();
        block_find_bin(hist, 1024, rB, sgrp, aux, tid, lane, w);
        unsigned thrkey = (bA << 21) | (bB << 10) | aux[0];    // exact key of k-th largest
        __syncthreads();

        for (int ww = 0; ww < NW_; ww++) {                     // candidates above thr
            unsigned c = wcnt[ww];
            const unsigned long long* rg = cd + (size_t)ww * CAP_;
            for (unsigned i = tid; i < c; i += NT_) {
                unsigned long long cc = rg[i];
                if ((unsigned)(cc >> 32) > thrkey) {
                    unsigned pos = (unsigned)cc & 0x3FFFFu;
                    atomicOr(&sbm[pos >> 5], 1u << (pos & 31u));
                }
            }
        }
        __syncthreads();
    }

    for (int j = tid; j < 8192; j += NT_)
        g_bitmap[(size_t)ch * 8192 + j] = sbm[j];
}

// K_mask: OR 9 channel bitmaps (smem-staged), apply to x.
__global__ void __launch_bounds__(256) k_mask(const float* __restrict__ x,
                                              float* __restrict__ out)
{
    __shared__ unsigned sw[32];
    int n = blockIdx.y;
    int i = blockIdx.x * 256 + threadIdx.x;          // float4 index within sample
    if (threadIdx.x < 32) {
        const unsigned* bm = g_bitmap + (size_t)n * C_ * 8192
                           + (size_t)blockIdx.x * 32 + threadIdx.x;
        unsigned o = 0;
        #pragma unroll
        for (int c = 0; c < C_; c++) o |= bm[(size_t)c * 8192];
        sw[threadIdx.x] = o;
    }
    __syncthreads();
    unsigned nib = (sw[threadIdx.x >> 3] >> ((threadIdx.x & 7) * 4)) & 0xFu;
    float4 xv = ((const float4*)(x + (size_t)n * HW_))[i];
    float4 o;
    o.x = (nib & 1u) ? 0.0f : xv.x;
    o.y = (nib & 2u) ? 0.0f : xv.y;
    o.z = (nib & 4u) ? 0.0f : xv.z;
    o.w = (nib & 8u) ? 0.0f : xv.w;
    ((float4*)out)[(size_t)n * (HW_ / 4) + i] = o;
}

extern "C" void kernel_launch(void* const* d_in, const int* in_sizes, int n_in,
                              void* d_out, int out_size) {
    const float* inp   = (const float*)d_in[0];   // [16,9,512,512]
    const float* x     = (const float*)d_in[1];   // [16,1,512,512]
    const float* ratio = (const float*)d_in[2];   // [16]
    float* out = (float*)d_out;

    k_main<<<NCH_, NT_>>>(inp, ratio);
    dim3 g(HW_ / 4 / 256, N_);
    k_mask<<<g, 256>>>(x, out);
}

// round 5
// speedup vs baseline: 7.9500x; 1.6538x over previous
#include <cuda_runtime.h>

#define HW_    262144          // 512*512
#define C_     9
#define N_     16
#define NCH_   144             // N_*C_
#define NT_    1024            // threads per CTA
#define SLOTS_ 256             // per-thread candidate slots (256*1024 = HW_, no overflow)

// Scratch (device globals — no allocation allowed)
__device__ unsigned long long g_cand[(size_t)NCH_ * HW_];  // per-thread regions
__device__ unsigned g_bitmap[NCH_ * (HW_ / 32)];           // per-channel mask bitmap
__device__ unsigned g_bar_cnt;                             // grid barrier (zero-init)
__device__ unsigned g_bar_flag;

// Order-preserving float->uint key (ascending key == ascending float)
static __device__ __forceinline__ unsigned f2key(float f) {
    unsigned u = __float_as_uint(f);
    return (u & 0x80000000u) ? ~u : (u | 0x80000000u);
}

// Block-wide "find bin containing rank-from-top" over hist[0..nb), nb in {2048,1024}.
// Result: aux[0]=bin, aux[1]=remaining rank (1-indexed in bin). All NT_ threads call.
static __device__ __forceinline__ void block_find_bin(
    unsigned* hist, int nb, unsigned rank,
    unsigned* sgrp, unsigned* aux, int tid, int lane, int w)
{
    unsigned s = (nb == 2048) ? (hist[tid * 2] + hist[tid * 2 + 1]) : hist[tid];
    sgrp[tid] = s;
    __syncthreads();
    if (w == 0) {
        unsigned sup = 0;
        #pragma unroll 4
        for (int j = 0; j < 32; j++) sup += sgrp[lane * 32 + j];
        unsigned v = sup;                    // inclusive suffix scan (lane31 = top bins)
        #pragma unroll
        for (int off = 1; off < 32; off <<= 1) {
            unsigned t = __shfl_down_sync(0xffffffffu, v, off);
            if (lane + off < 32) v += t;
        }
        unsigned cumAbove = v - sup;
        bool hit = (cumAbove < rank) && (cumAbove + sup >= rank);
        unsigned bal = __ballot_sync(0xffffffffu, hit);
        int Ls = __ffs(bal) - 1;
        if (lane == Ls) {
            unsigned cum = cumAbove;
            for (int g = Ls * 32 + 31; ; g--) {
                unsigned sg = sgrp[g];
                if (cum + sg >= rank) {
                    int B = (nb == 2048) ? 2 : 1;
                    for (int b = g * B + B - 1; ; b--) {
                        unsigned h = hist[b];
                        if (cum + h >= rank) { aux[0] = (unsigned)b; aux[1] = rank - cum; break; }
                        cum += h;
                    }
                    break;
                }
                cum += sg;
            }
        }
    }
    __syncthreads();
}

static __device__ __forceinline__ void cap_elem(
    unsigned long long* myc, int& mycap, unsigned c, const float4& v, int idx4)
{
    while (c) {
        int e = __ffs(c) - 1; c &= c - 1;
        float fv = (e == 0) ? v.x : (e == 1) ? v.y : (e == 2) ? v.z : v.w;
        myc[mycap++] = ((unsigned long long)f2key(fv) << 32) | (unsigned)(idx4 * 4 + e);
    }
}

__global__ void __launch_bounds__(NT_) k_fused(const float* __restrict__ inp,
                                               const float* __restrict__ ratio,
                                               const float* __restrict__ x,
                                               float* __restrict__ out)
{
    __shared__ unsigned hist[2048];
    __shared__ unsigned sbm[8192];     // channel mask bitmap (1 bit / pixel)
    __shared__ unsigned sgrp[NT_];
    __shared__ unsigned aux[4];        // [0]=cnt_hi / bin, [1]=m / rank

    int ch = blockIdx.x, n = ch / C_;
    int tid = threadIdx.x, w = tid >> 5, lane = tid & 31;

    // k: replicate reference f32 arithmetic exactly
    float f_p = floorf(ratio[n] * 262144.0f);
    int k = (int)floorf(f_p * 0.15f);
    bool k0 = (k <= 0);

    const float4* p = (const float4*)(inp + (size_t)ch * HW_);
    const float INF = __int_as_float(0x7F800000);

    // Analytic bracket around the k-th largest for N(0,1)-like data. Correctness
    // is guaranteed by the count-check + full-range retry, not by normality.
    float lo_f, hi_f;
    if (k0) {
        lo_f = hi_f = 1.0f;            // reference: thr = 1.0 when k == 0 (strict >)
    } else {
        float q = (float)k * (1.0f / 262144.0f);
        float t = sqrtf(-2.0f * logf(q));               // A&S 26.2.23
        float z = t - (2.515517f + 0.802853f * t + 0.010328f * t * t)
                    / (1.0f + 1.432788f * t + 0.189269f * t * t + 0.001308f * t * t * t);
        float phi = 0.3989423f * expf(-0.5f * z * z);
        float delta = 0.008f + 10.0f * sqrtf((float)k) / (262144.0f * phi);
        lo_f = z - delta; hi_f = z + delta;
    }

    unsigned long long* myc = g_cand + (size_t)ch * HW_ + (size_t)tid * SLOTS_;
    unsigned cnt_hi, m;
    int mycap;
    for (int attempt = 0; ; attempt++) {
        if (tid == 0) { aux[0] = 0; aux[1] = 0; }
        __syncthreads();
        unsigned mycnt = 0;
        mycap = 0;
        for (int base = 0; base < HW_ / 4; base += 4 * NT_) {
            // 4 loads in flight before any processing
            float4 v0 = p[base + tid];
            float4 v1 = p[base + NT_ + tid];
            float4 v2 = p[base + 2 * NT_ + tid];
            float4 v3 = p[base + 3 * NT_ + tid];
            unsigned ab[4], cn[4];
            {
                unsigned a, g;
                a = (unsigned)(v0.x > hi_f) | ((unsigned)(v0.y > hi_f) << 1)
                  | ((unsigned)(v0.z > hi_f) << 2) | ((unsigned)(v0.w > hi_f) << 3);
                g = (unsigned)(v0.x > lo_f) | ((unsigned)(v0.y > lo_f) << 1)
                  | ((unsigned)(v0.z > lo_f) << 2) | ((unsigned)(v0.w > lo_f) << 3);
                ab[0] = a; cn[0] = g & ~a;
                a = (unsigned)(v1.x > hi_f) | ((unsigned)(v1.y > hi_f) << 1)
                  | ((unsigned)(v1.z > hi_f) << 2) | ((unsigned)(v1.w > hi_f) << 3);
                g = (unsigned)(v1.x > lo_f) | ((unsigned)(v1.y > lo_f) << 1)
                  | ((unsigned)(v1.z > lo_f) << 2) | ((unsigned)(v1.w > lo_f) << 3);
                ab[1] = a; cn[1] = g & ~a;
                a = (unsigned)(v2.x > hi_f) | ((unsigned)(v2.y > hi_f) << 1)
                  | ((unsigned)(v2.z > hi_f) << 2) | ((unsigned)(v2.w > hi_f) << 3);
                g = (unsigned)(v2.x > lo_f) | ((unsigned)(v2.y > lo_f) << 1)
                  | ((unsigned)(v2.z > lo_f) << 2) | ((unsigned)(v2.w > lo_f) << 3);
                ab[2] = a; cn[2] = g & ~a;
                a = (unsigned)(v3.x > hi_f) | ((unsigned)(v3.y > hi_f) << 1)
                  | ((unsigned)(v3.z > hi_f) << 2) | ((unsigned)(v3.w > hi_f) << 3);
                g = (unsigned)(v3.x > lo_f) | ((unsigned)(v3.y > lo_f) << 1)
                  | ((unsigned)(v3.z > lo_f) << 2) | ((unsigned)(v3.w > lo_f) << 3);
                ab[3] = a; cn[3] = g & ~a;
            }
            mycnt += __popc(ab[0]) + __popc(ab[1]) + __popc(ab[2]) + __popc(ab[3]);
            unsigned sh = (lane & 7) * 4;
            #pragma unroll
            for (int j = 0; j < 4; j++) {
                unsigned word = ab[j] << sh;
                word |= __shfl_xor_sync(0xffffffffu, word, 1);
                word |= __shfl_xor_sync(0xffffffffu, word, 2);
                word |= __shfl_xor_sync(0xffffffffu, word, 4);
                if ((lane & 7) == 0) sbm[(base + j * NT_ + tid) >> 3] = word;
            }
            // Per-thread capture: rare, no warp collectives, no loop-carried chain
            if (cn[0] | cn[1] | cn[2] | cn[3]) {
                cap_elem(myc, mycap, cn[0], v0, base + tid);
                cap_elem(myc, mycap, cn[1], v1, base + NT_ + tid);
                cap_elem(myc, mycap, cn[2], v2, base + 2 * NT_ + tid);
                cap_elem(myc, mycap, cn[3], v3, base + 3 * NT_ + tid);
            }
        }
        // Block totals
        unsigned mc = (unsigned)mycap;
        #pragma unroll
        for (int off = 16; off; off >>= 1) {
            mycnt += __shfl_down_sync(0xffffffffu, mycnt, off);
            mc    += __shfl_down_sync(0xffffffffu, mc, off);
        }
        if (lane == 0) { atomicAdd(&aux[0], mycnt); atomicAdd(&aux[1], mc); }
        __syncthreads();
        cnt_hi = aux[0]; m = aux[1];
        if (k0) break;
        if ((cnt_hi < (unsigned)k && cnt_hi + m >= (unsigned)k) || attempt >= 1) break;
        lo_f = -INF; hi_f = INF;       // deterministic widen (count-check guarantee)
        __syncthreads();
    }

    // ---- exact threshold among candidates (11+11+10-bit radix), then fixups ----
    if (!k0) {
        unsigned r = (unsigned)k - cnt_hi;
        for (int i = tid; i < 2048; i += NT_) hist[i] = 0;
        __syncthreads();
        for (int i = 0; i < mycap; i++)
            atomicAdd(&hist[(unsigned)(myc[i] >> 32) >> 21], 1u);
        __syncthreads();
        block_find_bin(hist, 2048, r, sgrp, aux, tid, lane, w);
        unsigned bA = aux[0], rA = aux[1];
        __syncthreads();

        for (int i = tid; i < 2048; i += NT_) hist[i] = 0;
        __syncthreads();
        for (int i = 0; i < mycap; i++) {
            unsigned key = (unsigned)(myc[i] >> 32);
            if ((key >> 21) == bA) atomicAdd(&hist[(key >> 10) & 0x7FFu], 1u);
        }
        __syncthreads();
        block_find_bin(hist, 2048, rA, sgrp, aux, tid, lane, w);
        unsigned bB = aux[0], rB = aux[1];
        __syncthreads();

        for (int i = tid; i < 1024; i += NT_) hist[i] = 0;
        __syncthreads();
        for (int i = 0; i < mycap; i++) {
            unsigned key = (unsigned)(myc[i] >> 32);
            if ((key >> 21) == bA && ((key >> 10) & 0x7FFu) == bB)
                atomicAdd(&hist[key & 0x3FFu], 1u);
        }
        __syncthreads();
        block_find_bin(hist, 1024, rB, sgrp, aux, tid, lane, w);
        unsigned thrkey = (bA << 21) | (bB << 10) | aux[0];    // exact k-th largest
        __syncthreads();

        for (int i = 0; i < mycap; i++) {
            unsigned long long cc = myc[i];
            if ((unsigned)(cc >> 32) > thrkey) {
                unsigned pos = (unsigned)cc & 0x3FFFFu;
                atomicOr(&sbm[pos >> 5], 1u << (pos & 31u));
            }
        }
        __syncthreads();
    }

    for (int j = tid; j < 8192; j += NT_)
        g_bitmap[(size_t)ch * 8192 + j] = sbm[j];

    // ---- software grid barrier (all 144 CTAs resident; graph-replay safe) ----
    __threadfence();
    __syncthreads();
    if (tid == 0) {
        unsigned gen = *(volatile unsigned*)&g_bar_flag;
        unsigned t = atomicAdd(&g_bar_cnt, 1u);
        if (t == NCH_ - 1) {
            atomicExch(&g_bar_cnt, 0u);          // reset for next graph replay
            __threadfence();
            atomicAdd(&g_bar_flag, 1u);
        } else {
            while (*(volatile unsigned*)&g_bar_flag == gen) __nanosleep(64);
        }
        __threadfence();
    }
    __syncthreads();

    // ---- phase 2: OR 9 channel bitmaps, apply to x ----
    for (int g = blockIdx.x * NT_ + tid; g < N_ * (HW_ / 4); g += NCH_ * NT_) {
        int nn = g >> 16;                 // sample
        int i  = g & 65535;               // float4 index within sample
        const unsigned* bm = g_bitmap + (size_t)nn * C_ * 8192 + (i >> 3);
        unsigned wrd = 0;
        #pragma unroll
        for (int c = 0; c < C_; c++) wrd |= __ldg(bm + (size_t)c * 8192);
        unsigned nib = (wrd >> ((i & 7) * 4)) & 0xFu;
        float4 xv = ((const float4*)x)[g];
        float4 o;
        o.x = (nib & 1u) ? 0.0f : xv.x;
        o.y = (nib & 2u) ? 0.0f : xv.y;
        o.z = (nib & 4u) ? 0.0f : xv.z;
        o.w = (nib & 8u) ? 0.0f : xv.w;
        ((float4*)out)[g] = o;
    }
}

extern "C" void kernel_launch(void* const* d_in, const int* in_sizes, int n_in,
                              void* d_out, int out_size) {
    const float* inp   = (const float*)d_in[0];   // [16,9,512,512]
    const float* x     = (const float*)d_in[1];   // [16,1,512,512]
    const float* ratio = (const float*)d_in[2];   // [16]
    float* out = (float*)d_out;

    k_fused<<<NCH_, NT_>>>(inp, ratio, x, out);
}